// round 1
// baseline (speedup 1.0000x reference)
#include <cuda_runtime.h>
#include <math.h>

#define HEADS 8
#define DHK 8
#define DHV 16
#define DIM 128
#define INC 128
#define QKV 32
#define EPS 1e-5f
#define QSCALE 0.08838834764831845f   // 128^-0.5

// smem layout (floats):
//  q    [8][128]     @ 0
//  k    [8][128]     @ 1024
//  v    [16][128]    @ 2048
//  rel  [16][256]    @ 4096   (q_emb+k_emb rows 0..15; later reused for v_emb rows 16..31)
//  attn [128][129]   @ 8192   (xs[32][128] aliases this region during conv)
// total = 24704 floats = 98816 bytes -> 2 CTAs/SM

__global__ void __launch_bounds__(256, 2)
axial_fused_kernel(const float* __restrict__ x, const float* __restrict__ W,
                   const float* __restrict__ gamma, const float* __restrict__ beta,
                   const float* __restrict__ mean, const float* __restrict__ var,
                   const float* __restrict__ relative, float* __restrict__ out)
{
    extern __shared__ float sm[];
    float* q    = sm;
    float* k    = sm + 1024;
    float* v    = sm + 2048;
    float* rel  = sm + 4096;
    float* attn = sm + 8192;
    float* xs   = attn;          // alias: only live during conv phase

    const int t   = threadIdx.x;
    const int bid = blockIdx.x;
    const int b   = bid >> 3;
    const int h   = bid & 7;

    // ---------------- load q_emb + k_emb (relative rows 0..15) ----------------
    for (int idx = t; idx < 16 * 255; idx += 256) {
        int c = idx / 255, m = idx - c * 255;
        rel[c * 256 + m] = relative[idx];
    }

    // ---------------- conv + BN: qkv rows r = 0..31 for this head -------------
    const int r    = t & 31;       // qkv channel c
    const int dseg = t >> 5;       // 0..7 -> d in [dseg*16, dseg*16+16)
    const int o    = r * 8 + h;    // output channel o = c*HEADS + h

    float acc[16];
#pragma unroll
    for (int i = 0; i < 16; ++i) acc[i] = 0.f;

    const float* xb = x + (size_t)b * (INC * DIM);
    const float4* Wrow = reinterpret_cast<const float4*>(W + o * INC);

    for (int cc = 0; cc < 4; ++cc) {
        __syncthreads();
        // stage x[b][cc*32 .. cc*32+31][:] into xs (coalesced float4)
        const float4* src = reinterpret_cast<const float4*>(xb + cc * 32 * DIM);
        float4* dst = reinterpret_cast<float4*>(xs);
#pragma unroll
        for (int f = 0; f < 4; ++f) dst[t + 256 * f] = src[t + 256 * f];
        __syncthreads();

#pragma unroll
        for (int c4 = 0; c4 < 8; ++c4) {
            float4 wv = Wrow[cc * 8 + c4];
            float wc[4] = {wv.x, wv.y, wv.z, wv.w};
#pragma unroll
            for (int cu = 0; cu < 4; ++cu) {
                const float4* xr = reinterpret_cast<const float4*>(
                    xs + (c4 * 4 + cu) * DIM + dseg * 16);
                float w = wc[cu];
#pragma unroll
                for (int dd = 0; dd < 4; ++dd) {
                    float4 xv = xr[dd];
                    acc[dd * 4 + 0] += w * xv.x;
                    acc[dd * 4 + 1] += w * xv.y;
                    acc[dd * 4 + 2] += w * xv.z;
                    acc[dd * 4 + 3] += w * xv.w;
                }
            }
        }
    }

    // BN affine (+ q scaling) and write to q/k/v smem
    {
        float iv   = gamma[o] * rsqrtf(var[o] + EPS);
        float bias = beta[o] - mean[o] * iv;
        float qs   = (r < 8) ? QSCALE : 1.0f;
        float* dstrow = (r < 8) ? (q + r * DIM)
                                : (r < 16 ? (k + (r - 8) * DIM) : (v + (r - 16) * DIM));
#pragma unroll
        for (int dd4 = 0; dd4 < 4; ++dd4) {
            float4 s;
            s.x = (acc[dd4 * 4 + 0] * iv + bias) * qs;
            s.y = (acc[dd4 * 4 + 1] * iv + bias) * qs;
            s.z = (acc[dd4 * 4 + 2] * iv + bias) * qs;
            s.w = (acc[dd4 * 4 + 3] * iv + bias) * qs;
            reinterpret_cast<float4*>(dstrow + dseg * 16)[dd4] = s;
        }
    }
    __syncthreads();   // qkv ready; xs (attn alias) free for reuse

    // ---------------- logits: attn[d][j] = dots + qr + kr ---------------------
    // thread (ty,tx): d-tile ty*8..+8 (2 halves of 4), j-tile tx*8..+8
    {
        const int ty = t >> 4, tx = t & 15;
        const int j0 = tx * 8;
#pragma unroll
        for (int half = 0; half < 2; ++half) {
            const int d0  = ty * 8 + half * 4;
            const int mlo = d0 - j0 + 120;   // multiple of 4, in [0, 244]
            float lacc[4][8];
#pragma unroll
            for (int a = 0; a < 4; ++a)
#pragma unroll
                for (int bb = 0; bb < 8; ++bb) lacc[a][bb] = 0.f;

#pragma unroll
            for (int i = 0; i < 8; ++i) {
                float4 qv = *reinterpret_cast<const float4*>(q + i * DIM + d0);
                float4 kv4 = *reinterpret_cast<const float4*>(k + i * DIM + d0);
                float qd[4] = {qv.x, qv.y, qv.z, qv.w};
                float kd[4] = {kv4.x, kv4.y, kv4.z, kv4.w};
                float kj[8];
                *reinterpret_cast<float4*>(kj)     = *reinterpret_cast<const float4*>(k + i * DIM + j0);
                *reinterpret_cast<float4*>(kj + 4) = *reinterpret_cast<const float4*>(k + i * DIM + j0 + 4);

                float rq[12];
                *reinterpret_cast<float4*>(rq)     = *reinterpret_cast<const float4*>(rel + i * 256 + mlo);
                *reinterpret_cast<float4*>(rq + 4) = *reinterpret_cast<const float4*>(rel + i * 256 + mlo + 4);
                *reinterpret_cast<float4*>(rq + 8) = *reinterpret_cast<const float4*>(rel + i * 256 + mlo + 8);
#pragma unroll
                for (int a = 0; a < 4; ++a)
#pragma unroll
                    for (int bb = 0; bb < 8; ++bb) {
                        lacc[a][bb] += qd[a] * kj[bb];
                        lacc[a][bb] += qd[a] * rq[7 + a - bb];
                    }

                float rk[12];
                *reinterpret_cast<float4*>(rk)     = *reinterpret_cast<const float4*>(rel + (8 + i) * 256 + mlo);
                *reinterpret_cast<float4*>(rk + 4) = *reinterpret_cast<const float4*>(rel + (8 + i) * 256 + mlo + 4);
                *reinterpret_cast<float4*>(rk + 8) = *reinterpret_cast<const float4*>(rel + (8 + i) * 256 + mlo + 8);
#pragma unroll
                for (int a = 0; a < 4; ++a)
#pragma unroll
                    for (int bb = 0; bb < 8; ++bb)
                        lacc[a][bb] += kd[a] * rk[7 + a - bb];
            }
#pragma unroll
            for (int a = 0; a < 4; ++a) {
                float* dstl = attn + (d0 + a) * 129 + j0;
#pragma unroll
                for (int bb = 0; bb < 8; ++bb) dstl[bb] = lacc[a][bb];
            }
        }
    }
    __syncthreads();

    // ---------------- softmax (warp per 16 rows) + load v_emb -----------------
    for (int idx = t; idx < 16 * 255; idx += 256) {
        int c = idx / 255, m = idx - c * 255;
        rel[c * 256 + m] = relative[16 * 255 + idx];
    }
    {
        const int warp = t >> 5, lane = t & 31;
        for (int rr = 0; rr < 16; ++rr) {
            float* row = attn + (warp * 16 + rr) * 129;
            float x0 = row[lane * 4 + 0], x1 = row[lane * 4 + 1];
            float x2 = row[lane * 4 + 2], x3 = row[lane * 4 + 3];
            float mx = fmaxf(fmaxf(x0, x1), fmaxf(x2, x3));
#pragma unroll
            for (int off = 16; off > 0; off >>= 1)
                mx = fmaxf(mx, __shfl_xor_sync(0xffffffffu, mx, off));
            float e0 = __expf(x0 - mx), e1 = __expf(x1 - mx);
            float e2 = __expf(x2 - mx), e3 = __expf(x3 - mx);
            float s = e0 + e1 + e2 + e3;
#pragma unroll
            for (int off = 16; off > 0; off >>= 1)
                s += __shfl_xor_sync(0xffffffffu, s, off);
            float inv = 1.0f / s;
            row[lane * 4 + 0] = e0 * inv;
            row[lane * 4 + 1] = e1 * inv;
            row[lane * 4 + 2] = e2 * inv;
            row[lane * 4 + 3] = e3 * inv;
        }
    }
    __syncthreads();

    // ---------------- out + kv ------------------------------------------------
    // thread: d0o = 2*(t%64) (two d), i = 4*(t/64)+ii (four i)
    {
        const int a_  = t & 63;
        const int d0o = a_ * 2;
        const int g   = t >> 6;
        float ao[4][2], ak[4][2];
#pragma unroll
        for (int ii = 0; ii < 4; ++ii) {
            ao[ii][0] = ao[ii][1] = 0.f;
            ak[ii][0] = ak[ii][1] = 0.f;
        }
        const float* row0 = attn + d0o * 129;
        const float* row1 = attn + (d0o + 1) * 129;
        for (int j = 0; j < 128; ++j) {
            float at0 = row0[j];
            float at1 = row1[j];
            int mb = d0o - j + 127;
#pragma unroll
            for (int ii = 0; ii < 4; ++ii) {
                int i = g * 4 + ii;
                float vv = v[i * DIM + j];
                ao[ii][0] += at0 * vv;
                ao[ii][1] += at1 * vv;
                float r0 = rel[i * 256 + mb];
                float r1 = rel[i * 256 + mb + 1];
                ak[ii][0] += at0 * r0;
                ak[ii][1] += at1 * r1;
            }
        }
        float* ob = out + (size_t)b * (HEADS * DHV * DIM) + (h * DHV) * DIM;
#pragma unroll
        for (int ii = 0; ii < 4; ++ii) {
            int i = g * 4 + ii;
            float2 s;
            s.x = ao[ii][0] + ak[ii][0];
            s.y = ao[ii][1] + ak[ii][1];
            *reinterpret_cast<float2*>(ob + i * DIM + d0o) = s;
        }
    }
}

extern "C" void kernel_launch(void* const* d_in, const int* in_sizes, int n_in,
                              void* d_out, int out_size) {
    const float* x        = (const float*)d_in[0];
    const float* W        = (const float*)d_in[1];
    const float* gamma    = (const float*)d_in[2];
    const float* beta     = (const float*)d_in[3];
    const float* mean     = (const float*)d_in[4];
    const float* var      = (const float*)d_in[5];
    const float* relative = (const float*)d_in[6];
    float* out = (float*)d_out;

    int b = in_sizes[0] / (INC * DIM);
    const int smem = 24704 * (int)sizeof(float);   // 98816 B
    cudaFuncSetAttribute(axial_fused_kernel,
                         cudaFuncAttributeMaxDynamicSharedMemorySize, smem);
    axial_fused_kernel<<<b * HEADS, 256, smem>>>(x, W, gamma, beta, mean, var,
                                                 relative, out);
}

// round 2
// speedup vs baseline: 1.5220x; 1.5220x over previous
#include <cuda_runtime.h>
#include <math.h>

#define HEADS 8
#define DHK 8
#define DHV 16
#define DIM 128
#define INC 128
#define EPS 1e-5f
#define QSCALE 0.08838834764831845f   // 128^-0.5

typedef unsigned long long ull;

__device__ float g_qkv[2048 * 256 * 128];   // [b][h][r(0..31)][d]  (256 MB scratch)

__device__ __forceinline__ ull pk2(float a, float b) {
    ull r; asm("mov.b64 %0, {%1, %2};" : "=l"(r) : "f"(a), "f"(b)); return r;
}
__device__ __forceinline__ void upk2(ull v, float& a, float& b) {
    asm("mov.b64 {%0, %1}, %2;" : "=f"(a), "=f"(b) : "l"(v));
}
__device__ __forceinline__ ull fma2(ull a, ull b, ull c) {
    ull r; asm("fma.rn.f32x2 %0, %1, %2, %3;" : "=l"(r) : "l"(a), "l"(b), "l"(c));
    return r;
}

// ============================================================================
// Kernel A: conv1x1 + BN (+ q pre-scale) as per-batch GEMM
//   y[o][d] = sum_c W[o][c] * x[b][c][d], o = 0..255, d = 0..127
//   scratch layout: g_qkv[((b*8 + h)*32 + r)*128 + d], o = r*8 + h
// ============================================================================
#define AS_STRIDE 260           // 32 k-rows x 260 (padded, 16B-aligned rows)

__global__ void __launch_bounds__(512, 1)
conv_bn_kernel(const float* __restrict__ x, const float* __restrict__ W,
               const float* __restrict__ gamma, const float* __restrict__ beta,
               const float* __restrict__ mean, const float* __restrict__ var,
               float* __restrict__ qkv)
{
    extern __shared__ float sm[];
    float* As = sm;                    // [32][260] transposed W chunk (k-major)
    float* Bs = sm + 32 * AS_STRIDE;   // [32][128] x chunk

    const int b  = blockIdx.x;
    const int t  = threadIdx.x;
    const int rt = t >> 4, dt = t & 15;
    const int r0 = rt * 8, d0 = dt * 8;

    ull acc[8][4];
#pragma unroll
    for (int a = 0; a < 8; ++a)
#pragma unroll
        for (int p = 0; p < 4; ++p) acc[a][p] = 0ULL;

    const float* xb = x + (size_t)b * (INC * DIM);

    for (int cc = 0; cc < 4; ++cc) {
        __syncthreads();
        // stage W[0:256][cc*32 .. +32] transposed -> As[k'][o]
#pragma unroll
        for (int it = 0; it < 4; ++it) {
            int e4 = t + 512 * it;          // 0..2047
            int o  = e4 >> 3;
            int kq = (e4 & 7) * 4;
            float4 wv = *reinterpret_cast<const float4*>(W + o * INC + cc * 32 + kq);
            As[(kq + 0) * AS_STRIDE + o] = wv.x;
            As[(kq + 1) * AS_STRIDE + o] = wv.y;
            As[(kq + 2) * AS_STRIDE + o] = wv.z;
            As[(kq + 3) * AS_STRIDE + o] = wv.w;
        }
        // stage x[b][cc*32 .. +32][:] -> Bs[k'][d]
#pragma unroll
        for (int it = 0; it < 2; ++it) {
            int e4 = t + 512 * it;          // 0..1023
            int kq = e4 >> 5;
            int d4 = (e4 & 31) * 4;
            *reinterpret_cast<float4*>(Bs + kq * DIM + d4) =
                *reinterpret_cast<const float4*>(xb + (cc * 32 + kq) * DIM + d4);
        }
        __syncthreads();

#pragma unroll 8
        for (int kk = 0; kk < 32; ++kk) {
            const float* brow = Bs + kk * DIM + d0;
            ull x0 = *reinterpret_cast<const ull*>(brow + 0);
            ull x1 = *reinterpret_cast<const ull*>(brow + 2);
            ull x2 = *reinterpret_cast<const ull*>(brow + 4);
            ull x3 = *reinterpret_cast<const ull*>(brow + 6);
            float wv[8];
            *reinterpret_cast<float4*>(wv)     = *reinterpret_cast<const float4*>(As + kk * AS_STRIDE + r0);
            *reinterpret_cast<float4*>(wv + 4) = *reinterpret_cast<const float4*>(As + kk * AS_STRIDE + r0 + 4);
#pragma unroll
            for (int rr = 0; rr < 8; ++rr) {
                ull wp = pk2(wv[rr], wv[rr]);
                acc[rr][0] = fma2(x0, wp, acc[rr][0]);
                acc[rr][1] = fma2(x1, wp, acc[rr][1]);
                acc[rr][2] = fma2(x2, wp, acc[rr][2]);
                acc[rr][3] = fma2(x3, wp, acc[rr][3]);
            }
        }
    }

    // epilogue: BN + q scaling, store to scratch
#pragma unroll
    for (int rr = 0; rr < 8; ++rr) {
        int o = r0 + rr;
        float iv   = gamma[o] * rsqrtf(var[o] + EPS);
        float bias = beta[o] - mean[o] * iv;
        if (o < 64) { iv *= QSCALE; bias *= QSCALE; }
        int r = o >> 3, h = o & 7;
        float* dst = qkv + (size_t)b * 32768 + h * 4096 + r * 128 + d0;
        float v0, v1, v2, v3, v4, v5, v6, v7;
        upk2(acc[rr][0], v0, v1); upk2(acc[rr][1], v2, v3);
        upk2(acc[rr][2], v4, v5); upk2(acc[rr][3], v6, v7);
        float4 s0, s1;
        s0.x = v0 * iv + bias; s0.y = v1 * iv + bias;
        s0.z = v2 * iv + bias; s0.w = v3 * iv + bias;
        s1.x = v4 * iv + bias; s1.y = v5 * iv + bias;
        s1.z = v6 * iv + bias; s1.w = v7 * iv + bias;
        *reinterpret_cast<float4*>(dst)     = s0;
        *reinterpret_cast<float4*>(dst + 4) = s1;
    }
}

// ============================================================================
// Kernel B: attention per (b, h)
// smem (floats):
//  q     [8][128]   @ 0
//  k     [8][128]   @ 1024
//  v     [16][128]  @ 2048
//  relqk [16][256]  @ 4096   (q_emb rows 0..7, k_emb rows 8..15; later relv)
//  attnT [128][132] @ 8192   (transposed: attnT[j][d])
// total 25088 floats = 100352 B -> 2 CTAs/SM
// ============================================================================
#define AT_STRIDE 132

__global__ void __launch_bounds__(256, 2)
attn_kernel(const float* __restrict__ qkv, const float* __restrict__ relative,
            float* __restrict__ out)
{
    extern __shared__ float sm[];
    float* q     = sm;
    float* k     = sm + 1024;
    float* v     = sm + 2048;
    float* relqk = sm + 4096;
    float* attnT = sm + 8192;
    float* relv  = relqk;        // reused after logits

    const int t   = threadIdx.x;
    const int bid = blockIdx.x;
    const int b   = bid >> 3;
    const int h   = bid & 7;

    // ---- load q/k/v from scratch + relqk -----------------------------------
    {
        const float* src = qkv + (size_t)b * 32768 + h * 4096;
#pragma unroll
        for (int it = 0; it < 4; ++it) {
            int e4 = t + 256 * it;              // 0..1023
            int r  = e4 >> 5;
            int dw = (e4 & 31) * 4;
            float4 val = *reinterpret_cast<const float4*>(src + r * 128 + dw);
            float* dst = (r < 8) ? (q + r * 128)
                                 : (r < 16 ? (k + (r - 8) * 128) : (v + (r - 16) * 128));
            *reinterpret_cast<float4*>(dst + dw) = val;
        }
        for (int idx = t; idx < 16 * 255; idx += 256) {
            int c = idx / 255, m = idx - c * 255;
            relqk[c * 256 + m] = relative[idx];
        }
    }
    __syncthreads();

    // ---- logits: attnT[j][d] = dots + qr + kr ------------------------------
    {
        const int tx = t & 15, ty = t >> 4;
        const int d0 = tx * 8, j0 = ty * 8;
        const int base = d0 - j0 + 120;          // window base, in [0, 240]

        ull acc[8][4];
#pragma unroll
        for (int a = 0; a < 8; ++a)
#pragma unroll
            for (int p = 0; p < 4; ++p) acc[a][p] = 0ULL;

#pragma unroll 2
        for (int i = 0; i < 8; ++i) {
            const float* qi = q + i * 128;
            const float* ki = k + i * 128;
            ull qp[4], kp[4];
            {
                ulonglong2 a0 = *reinterpret_cast<const ulonglong2*>(qi + d0);
                ulonglong2 a1 = *reinterpret_cast<const ulonglong2*>(qi + d0 + 4);
                qp[0] = a0.x; qp[1] = a0.y; qp[2] = a1.x; qp[3] = a1.y;
                ulonglong2 b0 = *reinterpret_cast<const ulonglong2*>(ki + d0);
                ulonglong2 b1 = *reinterpret_cast<const ulonglong2*>(ki + d0 + 4);
                kp[0] = b0.x; kp[1] = b0.y; kp[2] = b1.x; kp[3] = b1.y;
            }
            // dots: q[i][d] * k[i][j]
            {
                float kj[8];
                *reinterpret_cast<float4*>(kj)     = *reinterpret_cast<const float4*>(ki + j0);
                *reinterpret_cast<float4*>(kj + 4) = *reinterpret_cast<const float4*>(ki + j0 + 4);
#pragma unroll
                for (int jj = 0; jj < 8; ++jj) {
                    ull kk2 = pk2(kj[jj], kj[jj]);
#pragma unroll
                    for (int p = 0; p < 4; ++p)
                        acc[jj][p] = fma2(qp[p], kk2, acc[jj][p]);
                }
            }
            // qr: q[i][d] * relq[i][d-j+127]
            {
                float w[16];
                const float* rr = relqk + i * 256 + base;
#pragma unroll
                for (int u = 0; u < 4; ++u)
                    *reinterpret_cast<float4*>(w + 4 * u) = *reinterpret_cast<const float4*>(rr + 4 * u);
#pragma unroll
                for (int jj = 0; jj < 8; ++jj)
#pragma unroll
                    for (int p = 0; p < 4; ++p) {
                        int a = 2 * p + 7 - jj;
                        acc[jj][p] = fma2(qp[p], pk2(w[a], w[a + 1]), acc[jj][p]);
                    }
            }
            // kr: k[i][d] * relk[i][d-j+127]
            {
                float w[16];
                const float* rr = relqk + (8 + i) * 256 + base;
#pragma unroll
                for (int u = 0; u < 4; ++u)
                    *reinterpret_cast<float4*>(w + 4 * u) = *reinterpret_cast<const float4*>(rr + 4 * u);
#pragma unroll
                for (int jj = 0; jj < 8; ++jj)
#pragma unroll
                    for (int p = 0; p < 4; ++p) {
                        int a = 2 * p + 7 - jj;
                        acc[jj][p] = fma2(kp[p], pk2(w[a], w[a + 1]), acc[jj][p]);
                    }
            }
        }
        // store transposed
#pragma unroll
        for (int jj = 0; jj < 8; ++jj) {
            float* dst = attnT + (j0 + jj) * AT_STRIDE + d0;
#pragma unroll
            for (int p = 0; p < 4; ++p) {
                float lo, hi;
                upk2(acc[jj][p], lo, hi);
                float2 s; s.x = lo; s.y = hi;
                *reinterpret_cast<float2*>(dst + 2 * p) = s;
            }
        }
    }
    __syncthreads();

    // ---- softmax over j (columns of attnT) on warps 0-3; relv load on 4-7 --
    if (t < 128) {
        const int d = t;
        float mx = -INFINITY;
#pragma unroll 4
        for (int j = 0; j < 128; ++j)
            mx = fmaxf(mx, attnT[j * AT_STRIDE + d]);
        float s = 0.f;
#pragma unroll 4
        for (int j = 0; j < 128; ++j) {
            float e = __expf(attnT[j * AT_STRIDE + d] - mx);
            attnT[j * AT_STRIDE + d] = e;
            s += e;
        }
        float inv = 1.0f / s;
#pragma unroll 4
        for (int j = 0; j < 128; ++j)
            attnT[j * AT_STRIDE + d] *= inv;
    } else {
        int tt = t - 128;
        for (int idx = tt; idx < 16 * 255; idx += 128) {
            int c = idx / 255, m = idx - c * 255;
            relv[c * 256 + m] = relative[16 * 255 + idx];
        }
    }
    __syncthreads();

    // ---- out + kv -----------------------------------------------------------
    {
        const int lane = t & 31;
        const int ig   = t >> 5;
        const int d0o  = lane * 4;
        const int i0   = ig * 2;

        ull acc[2][2];
        acc[0][0] = acc[0][1] = acc[1][0] = acc[1][1] = 0ULL;

        const float* v0  = v + i0 * 128;
        const float* v1  = v + (i0 + 1) * 128;
        const float* r0p = relv + i0 * 256;
        const float* r1p = relv + (i0 + 1) * 256;

        for (int g = 0; g < 32; ++g) {
            int basev = d0o + 124 - 4 * g;        // in [0, 248]
            float w0[8], w1[8];
            *reinterpret_cast<float4*>(w0)     = *reinterpret_cast<const float4*>(r0p + basev);
            *reinterpret_cast<float4*>(w0 + 4) = *reinterpret_cast<const float4*>(r0p + basev + 4);
            *reinterpret_cast<float4*>(w1)     = *reinterpret_cast<const float4*>(r1p + basev);
            *reinterpret_cast<float4*>(w1 + 4) = *reinterpret_cast<const float4*>(r1p + basev + 4);
#pragma unroll
            for (int jj = 0; jj < 4; ++jj) {
                int j = 4 * g + jj;
                ulonglong2 at = *reinterpret_cast<const ulonglong2*>(attnT + j * AT_STRIDE + d0o);
                float vj0 = v0[j], vj1 = v1[j];
                ull vp0 = pk2(vj0, vj0);
                ull vp1 = pk2(vj1, vj1);
                acc[0][0] = fma2(at.x, vp0, acc[0][0]);
                acc[0][1] = fma2(at.y, vp0, acc[0][1]);
                acc[1][0] = fma2(at.x, vp1, acc[1][0]);
                acc[1][1] = fma2(at.y, vp1, acc[1][1]);
                int a0 = 3 - jj;
                acc[0][0] = fma2(at.x, pk2(w0[a0],     w0[a0 + 1]), acc[0][0]);
                acc[0][1] = fma2(at.y, pk2(w0[a0 + 2], w0[a0 + 3]), acc[0][1]);
                acc[1][0] = fma2(at.x, pk2(w1[a0],     w1[a0 + 1]), acc[1][0]);
                acc[1][1] = fma2(at.y, pk2(w1[a0 + 2], w1[a0 + 3]), acc[1][1]);
            }
        }

        float* ob = out + (size_t)b * 16384 + h * 2048;
#pragma unroll
        for (int ii = 0; ii < 2; ++ii) {
            float4 s;
            upk2(acc[ii][0], s.x, s.y);
            upk2(acc[ii][1], s.z, s.w);
            *reinterpret_cast<float4*>(ob + (i0 + ii) * 128 + d0o) = s;
        }
    }
}

// ============================================================================
extern "C" void kernel_launch(void* const* d_in, const int* in_sizes, int n_in,
                              void* d_out, int out_size) {
    const float* x        = (const float*)d_in[0];
    const float* W        = (const float*)d_in[1];
    const float* gamma    = (const float*)d_in[2];
    const float* beta     = (const float*)d_in[3];
    const float* mean     = (const float*)d_in[4];
    const float* var      = (const float*)d_in[5];
    const float* relative = (const float*)d_in[6];
    float* out = (float*)d_out;

    int nb = in_sizes[0] / (INC * DIM);

    float* scratch;
    cudaGetSymbolAddress((void**)&scratch, g_qkv);

    const int smemA = (32 * AS_STRIDE + 32 * 128) * (int)sizeof(float);   // 49664
    const int smemB = 25088 * (int)sizeof(float);                          // 100352
    cudaFuncSetAttribute(conv_bn_kernel, cudaFuncAttributeMaxDynamicSharedMemorySize, smemA);
    cudaFuncSetAttribute(attn_kernel,    cudaFuncAttributeMaxDynamicSharedMemorySize, smemB);

    conv_bn_kernel<<<nb, 512, smemA>>>(x, W, gamma, beta, mean, var, scratch);
    attn_kernel<<<nb * HEADS, 256, smemB>>>(scratch, relative, out);
}